// round 1
// baseline (speedup 1.0000x reference)
#include <cuda_runtime.h>

#define TPB 128
#define W   1116

__device__ __forceinline__ float softf(float c, float t) {
    return copysignf(fmaxf(fabsf(c) - t, 0.0f), c);
}

__global__ void __launch_bounds__(TPB) wavelet_kernel(
    const float* __restrict__ x, const float* __restrict__ rawthr,
    float* __restrict__ out)
{
    // Decomposition low-pass filter (8 taps), exact constants from reference.
    constexpr float DLO[8] = {
        -0.010597401784997278f,  0.032883011666982945f,
         0.030841381835986965f, -0.18703481171888114f,
        -0.02798376941698385f,   0.6308807679295904f,
         0.7148465705525415f,    0.23037781330885523f };
    // DHI[k] = (-1)^(k+1) * DLO[7-k]
    constexpr float DHI[8] = {
        -0.23037781330885523f,   0.7148465705525415f,
        -0.6308807679295904f,   -0.02798376941698385f,
         0.18703481171888114f,   0.030841381835986965f,
        -0.032883011666982945f, -0.010597401784997278f };

    // Level lengths: input 1116, then 7 DWT levels.
    constexpr int NS_[8]  = {1116, 561, 284, 145, 76, 41, 24, 15};
    // Detail coefficient offsets (sizes 561,284,145,76,41,24,15; total 1146)
    constexpr int DOFF[7] = {0, 561, 845, 990, 1066, 1107, 1131};

    __shared__ __align__(16) float sA[1136];  // 8 front pad + 1116 + tail pad
    __shared__ __align__(16) float sB[584];   // 8 front pad + up to 562 + tail pad
    __shared__ float sD[1146];

    float* A = sA + 8;
    float* B = sB + 8;
    float* bufs[2] = {A, B};

    const int tid = threadIdx.x;
    const long row = blockIdx.x;
    const float thr = fmaxf(rawthr[0], 0.01f);

    // ---- Load row (float4: 1116 = 279 * 4, row stride 4464B is 16B aligned) ----
    const float4* xin = (const float4*)(x + row * W);
    for (int i = tid; i < W / 4; i += TPB)
        ((float4*)A)[i] = xin[i];
    if (tid < 8) { sA[tid] = 0.f; A[W + tid] = 0.f; sB[tid] = 0.f; }
    __syncthreads();

    // ---- Forward: 7 DWT levels, soft-threshold details (and final approx) ----
    #pragma unroll
    for (int l = 0; l < 7; l++) {
        const int nout = NS_[l + 1];
        const float* src = bufs[l & 1];
        float* dst = bufs[(l + 1) & 1];
        float* dd  = sD + DOFF[l];
        for (int i = tid; i < nout; i += TPB) {
            const float* xp = src + 2 * i + 1;
            float slo = 0.f, shi = 0.f;
            #pragma unroll
            for (int j = 0; j < 8; j++) {
                float v = xp[-j];             // zero pads cover OOB
                slo = fmaf(DLO[j], v, slo);
                shi = fmaf(DHI[j], v, shi);
            }
            dd[i]  = softf(shi, thr);
            dst[i] = (l == 6) ? softf(slo, thr) : slo;
        }
        // refresh tail zero pad (buffer reuse leaves stale longer-level data)
        if (tid < 8) dst[nout + tid] = 0.f;
        __syncthreads();
    }

    // ---- Inverse: 7 IDWT levels (truncation implicit via n = detail length) ----
    #pragma unroll
    for (int s = 6; s >= 0; s--) {
        const int n = NS_[s + 1];             // detail length = effective a length
        const float* a  = bufs[(s + 1) & 1];
        float* dst      = bufs[s & 1];
        const float* dd = sD + DOFF[s];
        for (int p = tid; p < n - 3; p += TPB) {
            float ye = 0.f, yo = 0.f;
            #pragma unroll
            for (int q = 0; q < 4; q++) {
                float av = a[p + 3 - q];
                float dv = dd[p + 3 - q];
                ye = fmaf(DLO[7 - 2 * q],  av, ye);   // rec_lo even taps
                ye = fmaf(DLO[2 * q],      dv, ye);   // rec_hi even taps
                yo = fmaf(DLO[6 - 2 * q],  av, yo);   // rec_lo odd taps
                yo = fmaf(-DLO[2 * q + 1], dv, yo);   // rec_hi odd taps
            }
            ((float2*)dst)[p] = make_float2(ye, yo);  // STS.64, conflict-free
        }
        __syncthreads();
    }

    // ---- Store (result of final IDWT is in A, length 1116) ----
    float4* o = (float4*)(out + row * W);
    for (int i = tid; i < W / 4; i += TPB)
        o[i] = ((const float4*)A)[i];
}

extern "C" void kernel_launch(void* const* d_in, const int* in_sizes, int n_in,
                              void* d_out, int out_size) {
    const float* x   = (const float*)d_in[0];
    const float* thr = (const float*)d_in[1];
    float* out = (float*)d_out;
    const int rows = in_sizes[0] / W;
    wavelet_kernel<<<rows, TPB>>>(x, thr, out);
}